// round 4
// baseline (speedup 1.0000x reference)
#include <cuda_runtime.h>

#define BB   4
#define SS   2048
#define DD   10
#define VV   32000
#define ROWS (BB*SS)
#define RPB  128       // rows per logits block

// scratch (device globals — no allocation allowed)
__device__ float g_Q[ROWS*DD];
__device__ float g_K[ROWS*DD];
__device__ float g_V[ROWS*DD];
__device__ float g_O[ROWS*DD];

// packed f32x2 FMA (Blackwell FFMA2) — doubles fp32 FMA throughput
__device__ __forceinline__ float2 ffma2(float2 a, float2 b, float2 c) {
    float2 d;
    asm("fma.rn.f32x2 %0, %1, %2, %3;"
        : "=l"(reinterpret_cast<unsigned long long&>(d))
        : "l"(reinterpret_cast<unsigned long long&>(a)),
          "l"(reinterpret_cast<unsigned long long&>(b)),
          "l"(reinterpret_cast<unsigned long long&>(c)));
    return d;
}

// no-op: shifts the ncu -s 5 -c 1 capture slot so logits gets profiled
__global__ void noop_kernel() {}

// ---------------------------------------------------------------------------
// Kernel 1: h = emb[x] + pos;  G = h @ W.T  for one of {Q,K,V} per blockIdx.y.
// ---------------------------------------------------------------------------
__global__ void __launch_bounds__(128) qkv_kernel(
    const int* __restrict__ x, const float* __restrict__ emb,
    const float* __restrict__ pos, const float* __restrict__ Wq,
    const float* __restrict__ Wk, const float* __restrict__ Wv)
{
    __shared__ float sw[DD*DD];
    const float* W = (blockIdx.y == 0) ? Wq : (blockIdx.y == 1) ? Wk : Wv;
    float*       G = (blockIdx.y == 0) ? g_Q : (blockIdx.y == 1) ? g_K : g_V;

    if (threadIdx.x < DD*DD/2)
        ((float2*)sw)[threadIdx.x] = __ldg((const float2*)W + threadIdx.x);

    int row = blockIdx.x * 128 + threadIdx.x;
    int s   = row & (SS - 1);
    int tok = x[row];

    float2 h2[5];
    const float2* ep = (const float2*)(emb + tok*DD);
    const float2* pp = (const float2*)(pos + s*DD);
#pragma unroll
    for (int e = 0; e < 5; e++) {
        float2 ee = __ldg(ep + e), qq = __ldg(pp + e);
        h2[e] = make_float2(ee.x + qq.x, ee.y + qq.y);
    }
    __syncthreads();

    float2* go = (float2*)(G + row*DD);
#pragma unroll
    for (int d = 0; d < DD; d += 2) {
        float2 s0 = make_float2(0.f, 0.f), s1 = s0;
        const float2* w0 = (const float2*)(sw + d*DD);
        const float2* w1 = (const float2*)(sw + (d+1)*DD);
#pragma unroll
        for (int e = 0; e < 5; e++) {
            s0 = ffma2(h2[e], w0[e], s0);
            s1 = ffma2(h2[e], w1[e], s1);
        }
        go[d >> 1] = make_float2(s0.x + s0.y, s1.x + s1.y);
    }
}

// ---------------------------------------------------------------------------
// Kernel 2: causal attention, f32x2-packed, LOAD-BALANCED.
// Block (k, b) handles the complementary row-group pair {k, 63-k}: total
// work per block is uniform (~64 t-iterations), so the 128-block grid runs
// as one balanced wave instead of a 1.7-wave ramp. 8 warps, 4 rows/warp.
// Masked entries contribute exactly 0 (== reference's exp(-1e9/sqrt(d))).
// ---------------------------------------------------------------------------
__global__ void __launch_bounds__(256) attn_kernel()
{
    int b    = blockIdx.y;
    int kblk = blockIdx.x;          // 0..31
    int warp = threadIdx.x >> 5;
    int lane = threadIdx.x & 31;
    const float inv_sqrt_d = 0.3162277660168379f;
    const float* Qb = g_Q + b*SS*DD;
    const float* Kb = g_K + b*SS*DD;
    const float* Vb = g_V + b*SS*DD;

#pragma unroll 1
    for (int g = 0; g < 2; g++) {
        int grp = g ? (63 - kblk) : kblk;
        int s0  = grp * 32 + warp * 4;

        float2 q2[4][5], acc[4][5];
        float  l[4];
#pragma unroll
        for (int r = 0; r < 4; r++) {
            l[r] = 0.f;
            const float2* qp = (const float2*)(Qb + (s0 + r)*DD);
#pragma unroll
            for (int e = 0; e < 5; e++) {
                q2[r][e]  = __ldg(qp + e);
                acc[r][e] = make_float2(0.f, 0.f);
            }
        }
        int smax = s0 + 3;
        for (int t = lane; t <= smax; t += 32) {
            float2 k2[5], v2[5];
            const float2* kp = (const float2*)(Kb + t*DD);
            const float2* vp = (const float2*)(Vb + t*DD);
#pragma unroll
            for (int e = 0; e < 5; e++) { k2[e] = __ldg(kp + e); v2[e] = __ldg(vp + e); }
#pragma unroll
            for (int r = 0; r < 4; r++) {
                float2 s2 = make_float2(0.f, 0.f);
#pragma unroll
                for (int e = 0; e < 5; e++) s2 = ffma2(q2[r][e], k2[e], s2);
                float sc = s2.x + s2.y;
                if (t <= s0 + r) {
                    float ex = __expf(sc * inv_sqrt_d);
                    l[r] += ex;
                    float2 e2 = make_float2(ex, ex);
#pragma unroll
                    for (int e = 0; e < 5; e++) acc[r][e] = ffma2(v2[e], e2, acc[r][e]);
                }
            }
        }
        // warp-wide butterfly reduction
#pragma unroll
        for (int off = 16; off > 0; off >>= 1) {
#pragma unroll
            for (int r = 0; r < 4; r++) {
                l[r] += __shfl_xor_sync(0xffffffffu, l[r], off);
#pragma unroll
                for (int e = 0; e < 5; e++) {
                    acc[r][e].x += __shfl_xor_sync(0xffffffffu, acc[r][e].x, off);
                    acc[r][e].y += __shfl_xor_sync(0xffffffffu, acc[r][e].y, off);
                }
            }
        }
#pragma unroll
        for (int r = 0; r < 4; r++) {
            float il = 1.f / l[r];
            if (lane < DD) {
                float v = (lane & 1) ? acc[r][lane >> 1].y : acc[r][lane >> 1].x;
                g_O[(b*SS + s0 + r)*DD + lane] = v * il;
            }
        }
    }
}

// ---------------------------------------------------------------------------
// Kernel 3: logits = out @ Wo.T  (1.048 GB f32 writes — DRAM-write bound).
// Block = 128 rows x 5 warps; warp owns 256 vocab as two 128-vocab chunks,
// lane owns 4 consecutive floats per chunk -> dense STG.128 (512 B/warp-op).
// Wo pairs in 80 regs reused across 128 rows; h duplicated as float2(h,h)
// in shared -> one LDS.64 broadcast per d.
// ---------------------------------------------------------------------------
__global__ void __launch_bounds__(160) logits_kernel(
    const float* __restrict__ Wo, float* __restrict__ out)
{
    __shared__ float2 sh[RPB*DD];
    int r0   = blockIdx.x * RPB;
    int tid  = threadIdx.x;
    int warp = tid >> 5;
    int lane = tid & 31;

    for (int i = tid; i < RPB*DD; i += 160) {
        float v = g_O[r0*DD + i];
        sh[i] = make_float2(v, v);
    }
    __syncthreads();

    int vbase = (blockIdx.y * 5 + warp) * 256 + lane * 4;

    float2 w[2][2][DD];   // [chunk][pair][d]
#pragma unroll
    for (int c = 0; c < 2; c++)
#pragma unroll
        for (int p = 0; p < 2; p++)
#pragma unroll
            for (int d = 0; d < DD; d++) {
                int v = vbase + c*128 + 2*p;
                w[c][p][d].x = __ldg(Wo + (v    )*DD + d);
                w[c][p][d].y = __ldg(Wo + (v + 1)*DD + d);
            }

#pragma unroll 1
    for (int s = 0; s < RPB; s++) {
        float2 a00 = make_float2(0.f, 0.f), a01 = a00, a10 = a00, a11 = a00;
#pragma unroll
        for (int d = 0; d < DD; d++) {
            float2 h2 = sh[s*DD + d];
            a00 = ffma2(w[0][0][d], h2, a00);
            a01 = ffma2(w[0][1][d], h2, a01);
            a10 = ffma2(w[1][0][d], h2, a10);
            a11 = ffma2(w[1][1][d], h2, a11);
        }
        size_t rowoff = (size_t)(r0 + s) * VV;
        __stcs(reinterpret_cast<float4*>(out + rowoff + vbase),
               make_float4(a00.x, a00.y, a01.x, a01.y));
        __stcs(reinterpret_cast<float4*>(out + rowoff + vbase + 128),
               make_float4(a10.x, a10.y, a11.x, a11.y));
    }
}

// ---------------------------------------------------------------------------
extern "C" void kernel_launch(void* const* d_in, const int* in_sizes, int n_in,
                              void* d_out, int out_size)
{
    const int*   x   = (const int*)  d_in[0];
    const float* emb = (const float*)d_in[1];
    const float* pos = (const float*)d_in[2];
    const float* Wq  = (const float*)d_in[3];
    const float* Wk  = (const float*)d_in[4];
    const float* Wv  = (const float*)d_in[5];
    const float* Wo  = (const float*)d_in[6];
    float* out = (float*)d_out;

    noop_kernel<<<1, 1>>>();   // shifts ncu capture slot toward logits_kernel
    qkv_kernel<<<dim3(ROWS / 128, 3), 128>>>(x, emb, pos, Wq, Wk, Wv);
    attn_kernel<<<dim3(SS / 64, BB), 256>>>();
    logits_kernel<<<dim3(ROWS / RPB, 25), 160>>>(Wo, out);
}

// round 5
// speedup vs baseline: 1.4382x; 1.4382x over previous
#include <cuda_runtime.h>

#define BB   4
#define SS   2048
#define DD   10
#define VV   32000
#define ROWS (BB*SS)
#define RPB  128       // rows per logits block
#define HST  12        // padded h stride (floats) for LDS.128

// scratch (device globals — no allocation allowed)
__device__ float g_Q[ROWS*DD];
__device__ float g_K[ROWS*DD];
__device__ float g_V[ROWS*DD];
__device__ float g_O[ROWS*DD];

// packed f32x2 FMA (Blackwell FFMA2) — doubles fp32 FMA throughput
__device__ __forceinline__ float2 ffma2(float2 a, float2 b, float2 c) {
    float2 d;
    asm("fma.rn.f32x2 %0, %1, %2, %3;"
        : "=l"(reinterpret_cast<unsigned long long&>(d))
        : "l"(reinterpret_cast<unsigned long long&>(a)),
          "l"(reinterpret_cast<unsigned long long&>(b)),
          "l"(reinterpret_cast<unsigned long long&>(c)));
    return d;
}

// no-op: keeps the ncu -s 5 -c 1 capture slot on logits_kernel
__global__ void noop_kernel() {}

// ---------------------------------------------------------------------------
// Kernel 1: h = emb[x] + pos;  G = h @ W.T  for one of {Q,K,V} per blockIdx.y.
// ---------------------------------------------------------------------------
__global__ void __launch_bounds__(128) qkv_kernel(
    const int* __restrict__ x, const float* __restrict__ emb,
    const float* __restrict__ pos, const float* __restrict__ Wq,
    const float* __restrict__ Wk, const float* __restrict__ Wv)
{
    __shared__ float sw[DD*DD];
    const float* W = (blockIdx.y == 0) ? Wq : (blockIdx.y == 1) ? Wk : Wv;
    float*       G = (blockIdx.y == 0) ? g_Q : (blockIdx.y == 1) ? g_K : g_V;

    if (threadIdx.x < DD*DD/2)
        ((float2*)sw)[threadIdx.x] = __ldg((const float2*)W + threadIdx.x);

    int row = blockIdx.x * 128 + threadIdx.x;
    int s   = row & (SS - 1);
    int tok = x[row];

    float2 h2[5];
    const float2* ep = (const float2*)(emb + tok*DD);
    const float2* pp = (const float2*)(pos + s*DD);
#pragma unroll
    for (int e = 0; e < 5; e++) {
        float2 ee = __ldg(ep + e), qq = __ldg(pp + e);
        h2[e] = make_float2(ee.x + qq.x, ee.y + qq.y);
    }
    __syncthreads();

    float2* go = (float2*)(G + row*DD);
#pragma unroll
    for (int d = 0; d < DD; d += 2) {
        float2 s0 = make_float2(0.f, 0.f), s1 = s0;
        const float2* w0 = (const float2*)(sw + d*DD);
        const float2* w1 = (const float2*)(sw + (d+1)*DD);
#pragma unroll
        for (int e = 0; e < 5; e++) {
            s0 = ffma2(h2[e], w0[e], s0);
            s1 = ffma2(h2[e], w1[e], s1);
        }
        go[d >> 1] = make_float2(s0.x + s0.y, s1.x + s1.y);
    }
}

// ---------------------------------------------------------------------------
// Kernel 2: causal attention (R3 version — reverted; the R4 pairing scheme
// regressed ~95us). Block = (32 rows, one batch), 4 rows per warp, f32x2.
// Masked entries contribute exactly 0 (== reference's exp(-1e9/sqrt(d))).
// ---------------------------------------------------------------------------
__global__ void __launch_bounds__(256) attn_kernel()
{
    int b    = blockIdx.y;
    int warp = threadIdx.x >> 5;
    int lane = threadIdx.x & 31;
    const float inv_sqrt_d = 0.3162277660168379f;
    const float* Qb = g_Q + b*SS*DD;
    const float* Kb = g_K + b*SS*DD;
    const float* Vb = g_V + b*SS*DD;

    int s0 = blockIdx.x * 32 + warp * 4;
    float2 q2[4][5], acc[4][5];
    float  l[4];
#pragma unroll
    for (int r = 0; r < 4; r++) {
        l[r] = 0.f;
        const float2* qp = (const float2*)(Qb + (s0 + r)*DD);
#pragma unroll
        for (int e = 0; e < 5; e++) {
            q2[r][e]  = __ldg(qp + e);
            acc[r][e] = make_float2(0.f, 0.f);
        }
    }
    int smax = s0 + 3;
    for (int t = lane; t <= smax; t += 32) {
        float2 k2[5], v2[5];
        const float2* kp = (const float2*)(Kb + t*DD);
        const float2* vp = (const float2*)(Vb + t*DD);
#pragma unroll
        for (int e = 0; e < 5; e++) { k2[e] = __ldg(kp + e); v2[e] = __ldg(vp + e); }
#pragma unroll
        for (int r = 0; r < 4; r++) {
            float2 s2 = make_float2(0.f, 0.f);
#pragma unroll
            for (int e = 0; e < 5; e++) s2 = ffma2(q2[r][e], k2[e], s2);
            float sc = s2.x + s2.y;
            if (t <= s0 + r) {
                float ex = __expf(sc * inv_sqrt_d);
                l[r] += ex;
                float2 e2 = make_float2(ex, ex);
#pragma unroll
                for (int e = 0; e < 5; e++) acc[r][e] = ffma2(v2[e], e2, acc[r][e]);
            }
        }
    }
    // warp-wide butterfly reduction
#pragma unroll
    for (int off = 16; off > 0; off >>= 1) {
#pragma unroll
        for (int r = 0; r < 4; r++) {
            l[r] += __shfl_xor_sync(0xffffffffu, l[r], off);
#pragma unroll
            for (int e = 0; e < 5; e++) {
                acc[r][e].x += __shfl_xor_sync(0xffffffffu, acc[r][e].x, off);
                acc[r][e].y += __shfl_xor_sync(0xffffffffu, acc[r][e].y, off);
            }
        }
    }
#pragma unroll
    for (int r = 0; r < 4; r++) {
        float il = 1.f / l[r];
        if (lane < DD) {
            float v = (lane & 1) ? acc[r][lane >> 1].y : acc[r][lane >> 1].x;
            g_O[(b*SS + s0 + r)*DD + lane] = v * il;
        }
    }
}

// ---------------------------------------------------------------------------
// Kernel 3: logits = out @ Wo.T  — profiled limiter was L1 (71%), not DRAM.
// L1 wavefronts/KB stored: was 10 LDS.64 + 8 STG = 18; now 3 LDS.128
// (broadcast, padded 12-float row stride) + 8 STG = 11. The (h,h) f32x2
// operands are built with MOVs on the near-idle ALU pipe instead of LDS.
// ---------------------------------------------------------------------------
__global__ void __launch_bounds__(160) logits_kernel(
    const float* __restrict__ Wo, float* __restrict__ out)
{
    __shared__ float sh[RPB*HST];
    int r0   = blockIdx.x * RPB;
    int tid  = threadIdx.x;
    int warp = tid >> 5;
    int lane = tid & 31;

    for (int i = tid; i < RPB*DD; i += 160) {
        int row = i / DD, d = i - row*DD;
        sh[row*HST + d] = g_O[r0*DD + i];
    }
    __syncthreads();

    int vbase = (blockIdx.y * 5 + warp) * 256 + lane * 4;

    float2 w[2][2][DD];   // [chunk][pair][d]
#pragma unroll
    for (int c = 0; c < 2; c++)
#pragma unroll
        for (int p = 0; p < 2; p++)
#pragma unroll
            for (int d = 0; d < DD; d++) {
                int v = vbase + c*128 + 2*p;
                w[c][p][d].x = __ldg(Wo + (v    )*DD + d);
                w[c][p][d].y = __ldg(Wo + (v + 1)*DD + d);
            }

#pragma unroll 1
    for (int s = 0; s < RPB; s++) {
        const float4* hp = reinterpret_cast<const float4*>(sh + s*HST);
        float4 p0 = hp[0];            // h0..h3
        float4 p1 = hp[1];            // h4..h7
        float4 p2 = hp[2];            // h8,h9,(pad,pad)
        float hv[DD] = {p0.x, p0.y, p0.z, p0.w, p1.x, p1.y, p1.z, p1.w, p2.x, p2.y};

        float2 a00 = make_float2(0.f, 0.f), a01 = a00, a10 = a00, a11 = a00;
#pragma unroll
        for (int d = 0; d < DD; d++) {
            float2 h2 = make_float2(hv[d], hv[d]);   // MOV-pack on ALU pipe
            a00 = ffma2(w[0][0][d], h2, a00);
            a01 = ffma2(w[0][1][d], h2, a01);
            a10 = ffma2(w[1][0][d], h2, a10);
            a11 = ffma2(w[1][1][d], h2, a11);
        }
        size_t rowoff = (size_t)(r0 + s) * VV;
        __stcs(reinterpret_cast<float4*>(out + rowoff + vbase),
               make_float4(a00.x, a00.y, a01.x, a01.y));
        __stcs(reinterpret_cast<float4*>(out + rowoff + vbase + 128),
               make_float4(a10.x, a10.y, a11.x, a11.y));
    }
}

// ---------------------------------------------------------------------------
extern "C" void kernel_launch(void* const* d_in, const int* in_sizes, int n_in,
                              void* d_out, int out_size)
{
    const int*   x   = (const int*)  d_in[0];
    const float* emb = (const float*)d_in[1];
    const float* pos = (const float*)d_in[2];
    const float* Wq  = (const float*)d_in[3];
    const float* Wk  = (const float*)d_in[4];
    const float* Wv  = (const float*)d_in[5];
    const float* Wo  = (const float*)d_in[6];
    float* out = (float*)d_out;

    noop_kernel<<<1, 1>>>();   // keeps ncu capture slot on logits_kernel
    qkv_kernel<<<dim3(ROWS / 128, 3), 128>>>(x, emb, pos, Wq, Wk, Wv);
    attn_kernel<<<dim3(SS / 32, BB), 256>>>();
    logits_kernel<<<dim3(ROWS / RPB, 25), 160>>>(Wo, out);
}